// round 1
// baseline (speedup 1.0000x reference)
#include <cuda_runtime.h>

#define NB   16
#define SEQ  1024
#define DIM  512
#define NH   8
#define DH   64

// Scratch (allocation-free: __device__ globals)
__device__ float g_Q[(size_t)NB*NH*SEQ*DH];
__device__ float g_K[(size_t)NB*NH*SEQ*DH];
__device__ float g_V[(size_t)NB*NH*SEQ*DH];
__device__ float g_AO[(size_t)NB*SEQ*DIM];

// ---------------------------------------------------------------------------
// Projection GEMM: Y = X @ W^T,  X:[16384,512], W:[512,512] row-major.
// Scatters into [b,h,n,d] layout for Q/K/V. Q pre-scaled by DH^-0.5.
// Tiles: BM=64, BN=64, BK=16; 256 threads; 4x4 micro-tile per thread.
// ---------------------------------------------------------------------------
__global__ void __launch_bounds__(256) proj_qkv_kernel(
    const float* __restrict__ X, const float* __restrict__ W,
    int which, float scale)
{
    __shared__ float As[16][64];
    __shared__ float Bs[16][64];
    float* __restrict__ Y = (which == 0) ? g_Q : (which == 1) ? g_K : g_V;

    const int tid  = threadIdx.x;
    const int tx   = tid & 15, ty = tid >> 4;
    const int m0   = blockIdx.y << 6;
    const int c0   = blockIdx.x << 6;
    const int lrow = tid >> 2;
    const int lk   = (tid & 3) << 2;

    float acc[4][4] = {};

    for (int k0 = 0; k0 < DIM; k0 += 16) {
        const float4 xa = *reinterpret_cast<const float4*>(&X[(size_t)(m0+lrow)*DIM + k0 + lk]);
        const float4 wb = *reinterpret_cast<const float4*>(&W[(size_t)(c0+lrow)*DIM + k0 + lk]);
        __syncthreads();
        As[lk+0][lrow]=xa.x; As[lk+1][lrow]=xa.y; As[lk+2][lrow]=xa.z; As[lk+3][lrow]=xa.w;
        Bs[lk+0][lrow]=wb.x; Bs[lk+1][lrow]=wb.y; Bs[lk+2][lrow]=wb.z; Bs[lk+3][lrow]=wb.w;
        __syncthreads();
        #pragma unroll
        for (int k = 0; k < 16; k++) {
            float a[4], b[4];
            #pragma unroll
            for (int r = 0; r < 4; r++) a[r] = As[k][(ty<<2)+r];
            #pragma unroll
            for (int c = 0; c < 4; c++) b[c] = Bs[k][(tx<<2)+c];
            #pragma unroll
            for (int r = 0; r < 4; r++)
                #pragma unroll
                for (int c = 0; c < 4; c++)
                    acc[r][c] = fmaf(a[r], b[c], acc[r][c]);
        }
    }

    #pragma unroll
    for (int r = 0; r < 4; r++) {
        const int m  = m0 + (ty<<2) + r;
        const int bb = m >> 10;          // m / SEQ
        const int i  = m & (SEQ - 1);
        #pragma unroll
        for (int c = 0; c < 4; c++) {
            const int col = c0 + (tx<<2) + c;
            const int h = col >> 6, d = col & 63;
            Y[(((size_t)bb*NH + h)*SEQ + i)*DH + d] = acc[r][c] * scale;
        }
    }
}

// ---------------------------------------------------------------------------
// Output projection GEMM: out = g_AO @ Wo^T, plain [m, col] layout.
// ---------------------------------------------------------------------------
__global__ void __launch_bounds__(256) proj_out_kernel(
    const float* __restrict__ W, float* __restrict__ out)
{
    __shared__ float As[16][64];
    __shared__ float Bs[16][64];

    const int tid  = threadIdx.x;
    const int tx   = tid & 15, ty = tid >> 4;
    const int m0   = blockIdx.y << 6;
    const int c0   = blockIdx.x << 6;
    const int lrow = tid >> 2;
    const int lk   = (tid & 3) << 2;

    float acc[4][4] = {};

    for (int k0 = 0; k0 < DIM; k0 += 16) {
        const float4 xa = *reinterpret_cast<const float4*>(&g_AO[(size_t)(m0+lrow)*DIM + k0 + lk]);
        const float4 wb = *reinterpret_cast<const float4*>(&W[(size_t)(c0+lrow)*DIM + k0 + lk]);
        __syncthreads();
        As[lk+0][lrow]=xa.x; As[lk+1][lrow]=xa.y; As[lk+2][lrow]=xa.z; As[lk+3][lrow]=xa.w;
        Bs[lk+0][lrow]=wb.x; Bs[lk+1][lrow]=wb.y; Bs[lk+2][lrow]=wb.z; Bs[lk+3][lrow]=wb.w;
        __syncthreads();
        #pragma unroll
        for (int k = 0; k < 16; k++) {
            float a[4], b[4];
            #pragma unroll
            for (int r = 0; r < 4; r++) a[r] = As[k][(ty<<2)+r];
            #pragma unroll
            for (int c = 0; c < 4; c++) b[c] = Bs[k][(tx<<2)+c];
            #pragma unroll
            for (int r = 0; r < 4; r++)
                #pragma unroll
                for (int c = 0; c < 4; c++)
                    acc[r][c] = fmaf(a[r], b[c], acc[r][c]);
        }
    }

    #pragma unroll
    for (int r = 0; r < 4; r++) {
        const int m = m0 + (ty<<2) + r;
        #pragma unroll
        for (int c = 0; c < 4; c++) {
            const int col = c0 + (tx<<2) + c;
            out[(size_t)m*DIM + col] = acc[r][c];
        }
    }
}

// ---------------------------------------------------------------------------
// Flash attention (fp32, online softmax).
// Block = one (b, h, 64-query tile). KV tiles of 64. 256 threads (16x16),
// each thread owns a 4x4 patch of S and a 4(rows)x4(d-cols) patch of O.
// Row-wise softmax stats reduced with shfl across the 16-thread tx group.
// ---------------------------------------------------------------------------
__global__ void __launch_bounds__(256) attn_kernel(const float* __restrict__ bias)
{
    extern __shared__ float sm[];
    float* Qs = sm;                 // [64][65]
    float* Ks = sm + 64*65;         // [64][65]
    float* Vs = sm + 2*64*65;       // [64][65]
    float* Ps = sm + 3*64*65;       // [64][65]

    const int tid = threadIdx.x;
    const int tx  = tid & 15, ty = tid >> 4;
    const int b   = blockIdx.z, h = blockIdx.y;
    const int i0  = blockIdx.x << 6;

    const float* __restrict__ Qg = g_Q + ((size_t)(b*NH + h)*SEQ + i0)*DH;
    const float* __restrict__ Kg = g_K + (size_t)(b*NH + h)*SEQ*DH;
    const float* __restrict__ Vg = g_V + (size_t)(b*NH + h)*SEQ*DH;
    const float* __restrict__ Bh = bias + (size_t)h*SEQ*SEQ;

    for (int t = tid; t < 64*64; t += 256) {
        const int i = t >> 6, d = t & 63;
        Qs[i*65 + d] = Qg[i*DH + d];
    }

    float m_run[4], l_run[4], o[4][4];
    #pragma unroll
    for (int r = 0; r < 4; r++) {
        m_run[r] = -1e30f; l_run[r] = 0.f;
        #pragma unroll
        for (int c = 0; c < 4; c++) o[r][c] = 0.f;
    }

    for (int j0 = 0; j0 < SEQ; j0 += 64) {
        __syncthreads();   // previous tile's Ps/Vs consumers done
        for (int t = tid; t < 64*64; t += 256) {
            const int j = t >> 6, d = t & 63;
            Ks[j*65 + d] = Kg[(size_t)(j0+j)*DH + d];
            Vs[j*65 + d] = Vg[(size_t)(j0+j)*DH + d];
        }
        __syncthreads();

        // S = Q K^T + bias   (Q already scaled at projection)
        float s[4][4];
        #pragma unroll
        for (int r = 0; r < 4; r++)
            #pragma unroll
            for (int c = 0; c < 4; c++)
                s[r][c] = Bh[(size_t)(i0 + (ty<<2) + r)*SEQ + j0 + (tx<<2) + c];

        #pragma unroll 8
        for (int d = 0; d < DH; d++) {
            float a[4], kk[4];
            #pragma unroll
            for (int r = 0; r < 4; r++) a[r]  = Qs[((ty<<2)+r)*65 + d];
            #pragma unroll
            for (int c = 0; c < 4; c++) kk[c] = Ks[((tx<<2)+c)*65 + d];
            #pragma unroll
            for (int r = 0; r < 4; r++)
                #pragma unroll
                for (int c = 0; c < 4; c++)
                    s[r][c] = fmaf(a[r], kk[c], s[r][c]);
        }

        // online softmax update (per row)
        #pragma unroll
        for (int r = 0; r < 4; r++) {
            float tm = fmaxf(fmaxf(s[r][0], s[r][1]), fmaxf(s[r][2], s[r][3]));
            #pragma unroll
            for (int off = 8; off > 0; off >>= 1)
                tm = fmaxf(tm, __shfl_xor_sync(0xffffffffu, tm, off));
            const float nm   = fmaxf(m_run[r], tm);
            const float corr = __expf(m_run[r] - nm);
            m_run[r] = nm;
            float ps = 0.f;
            #pragma unroll
            for (int c = 0; c < 4; c++) {
                const float p = __expf(s[r][c] - nm);
                s[r][c] = p; ps += p;
            }
            #pragma unroll
            for (int off = 8; off > 0; off >>= 1)
                ps += __shfl_xor_sync(0xffffffffu, ps, off);
            l_run[r] = l_run[r]*corr + ps;
            #pragma unroll
            for (int c = 0; c < 4; c++) o[r][c] *= corr;
        }

        // stage P through smem, then O += P @ V
        #pragma unroll
        for (int r = 0; r < 4; r++)
            #pragma unroll
            for (int c = 0; c < 4; c++)
                Ps[((ty<<2)+r)*65 + (tx<<2)+c] = s[r][c];
        __syncthreads();

        #pragma unroll 8
        for (int j = 0; j < 64; j++) {
            float p[4], v[4];
            #pragma unroll
            for (int r = 0; r < 4; r++) p[r] = Ps[((ty<<2)+r)*65 + j];
            #pragma unroll
            for (int c = 0; c < 4; c++) v[c] = Vs[j*65 + (tx<<2)+c];
            #pragma unroll
            for (int r = 0; r < 4; r++)
                #pragma unroll
                for (int c = 0; c < 4; c++)
                    o[r][c] = fmaf(p[r], v[c], o[r][c]);
        }
    }

    // normalize and write to [b, n, h*DH+d] so output proj is a plain GEMM
    #pragma unroll
    for (int r = 0; r < 4; r++) {
        const float inv = 1.f / l_run[r];
        const int gi = i0 + (ty<<2) + r;
        #pragma unroll
        for (int c = 0; c < 4; c++)
            g_AO[((size_t)b*SEQ + gi)*DIM + h*DH + (tx<<2) + c] = o[r][c] * inv;
    }
}

// ---------------------------------------------------------------------------
extern "C" void kernel_launch(void* const* d_in, const int* in_sizes, int n_in,
                              void* d_out, int out_size)
{
    const float* x    = (const float*)d_in[0];
    const float* bias = (const float*)d_in[1];
    const float* Wq   = (const float*)d_in[2];
    const float* Wk   = (const float*)d_in[3];
    const float* Wv   = (const float*)d_in[4];
    const float* Wo   = (const float*)d_in[5];
    float* out = (float*)d_out;

    const dim3 gblk(256);
    const dim3 ggrid(DIM/64, (NB*SEQ)/64);   // (8, 256)

    proj_qkv_kernel<<<ggrid, gblk>>>(x, Wq, 0, 0.125f);  // q * DH^-0.5
    proj_qkv_kernel<<<ggrid, gblk>>>(x, Wk, 1, 1.0f);
    proj_qkv_kernel<<<ggrid, gblk>>>(x, Wv, 2, 1.0f);

    const int smem = 4 * 64 * 65 * (int)sizeof(float);   // 66,560 B
    cudaFuncSetAttribute(attn_kernel, cudaFuncAttributeMaxDynamicSharedMemorySize, smem);
    attn_kernel<<<dim3(SEQ/64, NH, NB), 256, smem>>>(bias);

    proj_out_kernel<<<ggrid, gblk>>>(Wo, out);
}

// round 2
// speedup vs baseline: 3.3927x; 3.3927x over previous
#include <cuda_runtime.h>
#include <cstdint>

#define NB   16
#define SEQ  1024
#define DIM  512
#define NH   8
#define DH   64

// Scratch (allocation-free: __device__ globals)
__device__ float g_Q[(size_t)NB*NH*SEQ*DH];
__device__ float g_K[(size_t)NB*NH*SEQ*DH];
__device__ float g_V[(size_t)NB*NH*SEQ*DH];
__device__ float g_AO[(size_t)NB*SEQ*DIM];

__device__ __forceinline__ uint32_t f2tf(float f) {
    uint32_t u;
    asm("cvt.rna.tf32.f32 %0, %1;" : "=r"(u) : "f"(f));
    return u;
}

__device__ __forceinline__ void mma8(float c[4], const uint32_t a[4], const uint32_t b[2]) {
    asm volatile(
        "mma.sync.aligned.m16n8k8.row.col.f32.tf32.tf32.f32 "
        "{%0,%1,%2,%3}, {%4,%5,%6,%7}, {%8,%9}, {%0,%1,%2,%3};"
        : "+f"(c[0]), "+f"(c[1]), "+f"(c[2]), "+f"(c[3])
        : "r"(a[0]), "r"(a[1]), "r"(a[2]), "r"(a[3]), "r"(b[0]), "r"(b[1]));
}

// ---------------------------------------------------------------------------
// GEMM: Y = X @ W^T.  X:[16384,512], W:[512,512] row-major.
// BM=128, BN=128, BK=32; 256 threads = 8 warps (4m x 2n), warp tile 32x64.
// mode 0/1/2 -> scatter into g_Q/g_K/g_V as [b,h,n,d]; mode 3 -> plain Y.
// X == nullptr means "read from g_AO" (output projection).
// smem pitches chosen for conflict-free tf32 fragment loads (pitch 36).
// ---------------------------------------------------------------------------
__global__ void __launch_bounds__(256) proj_kernel(
    const float* __restrict__ X, const float* __restrict__ W,
    float* __restrict__ Yplain, int mode, float scale)
{
    __shared__ uint32_t As[128*36];
    __shared__ uint32_t Bs[128*36];

    const float* __restrict__ Xp = X ? X : g_AO;
    const int tid  = threadIdx.x;
    const int lane = tid & 31, warp = tid >> 5;
    const int q    = lane & 3, l4 = lane >> 2;
    const int wm   = warp >> 1, wn = warp & 1;
    const int m0   = blockIdx.y << 7;
    const int c0   = blockIdx.x << 7;

    float acc[2][8][4] = {};

    for (int k0 = 0; k0 < DIM; k0 += 32) {
        __syncthreads();
        #pragma unroll
        for (int t = 0; t < 4; t++) {
            const int f   = tid + t*256;
            const int row = f >> 3, c4 = (f & 7) << 2;
            const float4 xa = *(const float4*)&Xp[(size_t)(m0+row)*DIM + k0 + c4];
            As[row*36 + c4 + 0] = f2tf(xa.x);
            As[row*36 + c4 + 1] = f2tf(xa.y);
            As[row*36 + c4 + 2] = f2tf(xa.z);
            As[row*36 + c4 + 3] = f2tf(xa.w);
            const float4 wb = *(const float4*)&W[(size_t)(c0+row)*DIM + k0 + c4];
            Bs[row*36 + c4 + 0] = f2tf(wb.x);
            Bs[row*36 + c4 + 1] = f2tf(wb.y);
            Bs[row*36 + c4 + 2] = f2tf(wb.z);
            Bs[row*36 + c4 + 3] = f2tf(wb.w);
        }
        __syncthreads();

        #pragma unroll
        for (int ks = 0; ks < 4; ks++) {
            const int ko = ks << 3;
            uint32_t a[2][4];
            #pragma unroll
            for (int mt = 0; mt < 2; mt++) {
                const int r = wm*32 + mt*16 + l4;
                a[mt][0] = As[r*36     + ko + q];
                a[mt][1] = As[(r+8)*36 + ko + q];
                a[mt][2] = As[r*36     + ko + q + 4];
                a[mt][3] = As[(r+8)*36 + ko + q + 4];
            }
            #pragma unroll
            for (int nt = 0; nt < 8; nt++) {
                const int n = wn*64 + nt*8 + l4;
                uint32_t b[2] = { Bs[n*36 + ko + q], Bs[n*36 + ko + q + 4] };
                mma8(acc[0][nt], a[0], b);
                mma8(acc[1][nt], a[1], b);
            }
        }
    }

    // epilogue
    float* __restrict__ Ysc = (mode == 0) ? g_Q : (mode == 1) ? g_K : g_V;
    #pragma unroll
    for (int mt = 0; mt < 2; mt++) {
        #pragma unroll
        for (int half = 0; half < 2; half++) {
            const int m = m0 + wm*32 + mt*16 + l4 + half*8;
            #pragma unroll
            for (int nt = 0; nt < 8; nt++) {
                const int col = c0 + wn*64 + nt*8 + 2*q;
                const float v0 = acc[mt][nt][half*2 + 0] * scale;
                const float v1 = acc[mt][nt][half*2 + 1] * scale;
                if (mode < 3) {
                    const int bb = m >> 10, i = m & (SEQ-1);
                    const int h = col >> 6, d = col & 63;
                    *(float2*)&Ysc[(((size_t)bb*NH + h)*SEQ + i)*DH + d] = make_float2(v0, v1);
                } else {
                    *(float2*)&Yplain[(size_t)m*DIM + col] = make_float2(v0, v1);
                }
            }
        }
    }
}

// ---------------------------------------------------------------------------
// Flash attention, tf32 mma. Block = (b, h, 128-query tile); KV tiles of 64.
// 256 threads = 8 warps, each warp owns a full 16(row) x 64(key) S stripe
// (so softmax row stats reduce within a quad, P->PV needs only __syncwarp).
// smem: Qs[128][68], Ks[64][68], Vs[64][72], Ps[128][68] (bias staging + P).
// ---------------------------------------------------------------------------
__global__ void __launch_bounds__(256, 2) attn_kernel(const float* __restrict__ bias)
{
    extern __shared__ uint32_t sm[];
    uint32_t* Qs = sm;                   // 128*68
    uint32_t* Ks = sm + 128*68;          // 64*68
    uint32_t* Vs = Ks + 64*68;           // 64*72
    uint32_t* Ps = Vs + 64*72;           // 128*68
    float*    Pf = (float*)Ps;

    const int tid  = threadIdx.x;
    const int lane = tid & 31, warp = tid >> 5;
    const int q    = lane & 3, l4 = lane >> 2;
    const int b    = blockIdx.z, h = blockIdx.y;
    const int i0   = blockIdx.x << 7;
    const int r0   = warp*16 + l4;

    const float* __restrict__ Qg = g_Q + ((size_t)(b*NH + h)*SEQ + i0)*DH;
    const float* __restrict__ Kg = g_K + (size_t)(b*NH + h)*SEQ*DH;
    const float* __restrict__ Vg = g_V + (size_t)(b*NH + h)*SEQ*DH;
    const float* __restrict__ Bh = bias + (size_t)h*SEQ*SEQ + (size_t)i0*SEQ;

    // load Q tile (tf32)
    #pragma unroll
    for (int t = 0; t < 8; t++) {
        const int f = tid + t*256;
        const int row = f >> 4, c4 = (f & 15) << 2;
        const float4 v = *(const float4*)&Qg[(size_t)row*DH + c4];
        Qs[row*68 + c4 + 0] = f2tf(v.x);
        Qs[row*68 + c4 + 1] = f2tf(v.y);
        Qs[row*68 + c4 + 2] = f2tf(v.z);
        Qs[row*68 + c4 + 3] = f2tf(v.w);
    }

    float o[8][4] = {};
    float mrun[2] = {-1e30f, -1e30f}, lrun[2] = {0.f, 0.f};

    for (int j0 = 0; j0 < SEQ; j0 += 64) {
        __syncthreads();   // previous tile's Ks/Vs/Ps consumers done
        #pragma unroll
        for (int t = 0; t < 4; t++) {
            const int f = tid + t*256;
            const int row = f >> 4, c4 = (f & 15) << 2;
            const float4 kk = *(const float4*)&Kg[(size_t)(j0+row)*DH + c4];
            Ks[row*68 + c4 + 0] = f2tf(kk.x);
            Ks[row*68 + c4 + 1] = f2tf(kk.y);
            Ks[row*68 + c4 + 2] = f2tf(kk.z);
            Ks[row*68 + c4 + 3] = f2tf(kk.w);
            const float4 vv = *(const float4*)&Vg[(size_t)(j0+row)*DH + c4];
            Vs[row*72 + c4 + 0] = f2tf(vv.x);
            Vs[row*72 + c4 + 1] = f2tf(vv.y);
            Vs[row*72 + c4 + 2] = f2tf(vv.z);
            Vs[row*72 + c4 + 3] = f2tf(vv.w);
        }
        // bias tile -> Ps (raw fp32, coalesced)
        #pragma unroll
        for (int t = 0; t < 8; t++) {
            const int f = tid + t*256;
            const int row = f >> 4, c4 = (f & 15) << 2;
            const float4 bb = *(const float4*)&Bh[(size_t)row*SEQ + j0 + c4];
            Pf[row*68 + c4 + 0] = bb.x;
            Pf[row*68 + c4 + 1] = bb.y;
            Pf[row*68 + c4 + 2] = bb.z;
            Pf[row*68 + c4 + 3] = bb.w;
        }
        __syncthreads();

        // S = bias, then S += Q K^T
        float s[8][4];
        #pragma unroll
        for (int nt = 0; nt < 8; nt++) {
            const int col = nt*8 + 2*q;
            s[nt][0] = Pf[r0*68 + col];
            s[nt][1] = Pf[r0*68 + col + 1];
            s[nt][2] = Pf[(r0+8)*68 + col];
            s[nt][3] = Pf[(r0+8)*68 + col + 1];
        }
        #pragma unroll
        for (int ks = 0; ks < 8; ks++) {
            const int ko = ks << 3;
            uint32_t a[4] = { Qs[r0*68 + ko + q],     Qs[(r0+8)*68 + ko + q],
                              Qs[r0*68 + ko + q + 4], Qs[(r0+8)*68 + ko + q + 4] };
            #pragma unroll
            for (int nt = 0; nt < 8; nt++) {
                const int col = nt*8 + l4;
                uint32_t bf[2] = { Ks[col*68 + ko + q], Ks[col*68 + ko + q + 4] };
                mma8(s[nt], a, bf);
            }
        }

        // online softmax (row stats live in each quad)
        #pragma unroll
        for (int half = 0; half < 2; half++) {
            float rm = -1e30f;
            #pragma unroll
            for (int nt = 0; nt < 8; nt++)
                rm = fmaxf(rm, fmaxf(s[nt][half*2], s[nt][half*2+1]));
            rm = fmaxf(rm, __shfl_xor_sync(0xffffffffu, rm, 1));
            rm = fmaxf(rm, __shfl_xor_sync(0xffffffffu, rm, 2));
            const float nm   = fmaxf(mrun[half], rm);
            const float corr = __expf(mrun[half] - nm);
            mrun[half] = nm;
            float rs = 0.f;
            #pragma unroll
            for (int nt = 0; nt < 8; nt++) {
                const float p0 = __expf(s[nt][half*2]   - nm);
                const float p1 = __expf(s[nt][half*2+1] - nm);
                s[nt][half*2] = p0; s[nt][half*2+1] = p1;
                rs += p0 + p1;
            }
            rs += __shfl_xor_sync(0xffffffffu, rs, 1);
            rs += __shfl_xor_sync(0xffffffffu, rs, 2);
            lrun[half] = lrun[half]*corr + rs;
            #pragma unroll
            for (int nt = 0; nt < 8; nt++) {
                o[nt][half*2]   *= corr;
                o[nt][half*2+1] *= corr;
            }
        }

        // write P (tf32) to own stripe; only intra-warp consumers
        #pragma unroll
        for (int nt = 0; nt < 8; nt++) {
            const int col = nt*8 + 2*q;
            Ps[r0*68 + col]       = f2tf(s[nt][0]);
            Ps[r0*68 + col + 1]   = f2tf(s[nt][1]);
            Ps[(r0+8)*68 + col]   = f2tf(s[nt][2]);
            Ps[(r0+8)*68 + col+1] = f2tf(s[nt][3]);
        }
        __syncwarp();

        // O += P @ V
        #pragma unroll
        for (int ks = 0; ks < 8; ks++) {
            const int ko = ks << 3;
            uint32_t a[4] = { Ps[r0*68 + ko + q],     Ps[(r0+8)*68 + ko + q],
                              Ps[r0*68 + ko + q + 4], Ps[(r0+8)*68 + ko + q + 4] };
            #pragma unroll
            for (int nt = 0; nt < 8; nt++) {
                const int d = nt*8 + l4;
                uint32_t bf[2] = { Vs[(ko+q)*72 + d], Vs[(ko+q+4)*72 + d] };
                mma8(o[nt], a, bf);
            }
        }
    }

    // normalize + write [b, n, h*64+d] for the O projection
    #pragma unroll
    for (int half = 0; half < 2; half++) {
        const float inv = 1.f / lrun[half];
        const int gi = i0 + r0 + half*8;
        #pragma unroll
        for (int nt = 0; nt < 8; nt++) {
            const int d = nt*8 + 2*q;
            *(float2*)&g_AO[((size_t)b*SEQ + gi)*DIM + h*DH + d] =
                make_float2(o[nt][half*2]*inv, o[nt][half*2+1]*inv);
        }
    }
}

// ---------------------------------------------------------------------------
extern "C" void kernel_launch(void* const* d_in, const int* in_sizes, int n_in,
                              void* d_out, int out_size)
{
    const float* x    = (const float*)d_in[0];
    const float* bias = (const float*)d_in[1];
    const float* Wq   = (const float*)d_in[2];
    const float* Wk   = (const float*)d_in[3];
    const float* Wv   = (const float*)d_in[4];
    const float* Wo   = (const float*)d_in[5];
    float* out = (float*)d_out;

    const dim3 pgrid(DIM/128, (NB*SEQ)/128);   // (4, 128)
    proj_kernel<<<pgrid, 256>>>(x, Wq, nullptr, 0, 0.125f);  // Q * DH^-0.5
    proj_kernel<<<pgrid, 256>>>(x, Wk, nullptr, 1, 1.0f);
    proj_kernel<<<pgrid, 256>>>(x, Wv, nullptr, 2, 1.0f);

    const int smem = (128*68 + 64*68 + 64*72 + 128*68) * (int)sizeof(uint32_t); // 105,472 B
    cudaFuncSetAttribute(attn_kernel, cudaFuncAttributeMaxDynamicSharedMemorySize, smem);
    attn_kernel<<<dim3(SEQ/128, NH, NB), 256, smem>>>(bias);

    proj_kernel<<<pgrid, 256>>>(nullptr, Wo, out, 3, 1.0f);
}